// round 13
// baseline (speedup 1.0000x reference)
#include <cuda_runtime.h>
#include <cuda_bf16.h>
#include <math.h>

// ---------------------------------------------------------------------------
// DVDMixer: B = 32*128 = 4096 rows
// N_AGENTS=16, RNN_H=64, N_HEADS=4, GAT_D=32, EMB=32, SDIM=128
// fp32 CUDA-core implementation (tcgen05 not reachable through this harness
// toolchain — plain sm_103 ptxas pass; evidence R6-R9).
// ---------------------------------------------------------------------------

#define BROWS 4096

__device__ float g_buf[(size_t)BROWS * 4 * 16 * 32];   // 33.5 MB (L2-resident)
__device__ float epi_buf[(size_t)BROWS * 65];          // b1v | |wf| | v

__device__ __forceinline__ float fexp(float x) { return __expf(x); }
__device__ __forceinline__ float felu(float x) {
    return x > 0.f ? x : (__expf(x) - 1.f);
}

// ============================= Kernel A: GAT + epilogue prep ================
// (R11 version: two heads per hp pass — measured ~65us)
#define GAT_SMEM_FLOATS (8192 + 2560)

#define GAT_ATT(HP, H)                                                        \
    {                                                                         \
        const float asrc = __ldg(att + (H) * 64 + lane);                      \
        const float adst = __ldg(att + (H) * 64 + 32 + lane);                 \
        float srcv[16], dstv[16];                                             \
        _Pragma("unroll")                                                     \
        for (int n = 0; n < 16; n++) {                                        \
            float ps = HP[n] * asrc, pd = HP[n] * adst;                       \
            _Pragma("unroll")                                                 \
            for (int d = 16; d; d >>= 1) {                                    \
                ps += __shfl_xor_sync(0xffffffffu, ps, d);                    \
                pd += __shfl_xor_sync(0xffffffffu, pd, d);                    \
            }                                                                 \
            srcv[n] = ps; dstv[n] = pd;                                       \
        }                                                                     \
        {                                                                     \
            const int i  = lane & 15;                                         \
            const int jb = (lane >> 4) * 8;                                   \
            float e[8], mx = -1e30f;                                          \
            _Pragma("unroll")                                                 \
            for (int jj = 0; jj < 8; jj++) {                                  \
                float x = srcv[i] + dstv[jb + jj];                            \
                x = x > 0.f ? x : 0.2f * x;                                   \
                e[jj] = x;                                                    \
                mx = fmaxf(mx, x);                                            \
            }                                                                 \
            mx = fmaxf(mx, __shfl_xor_sync(0xffffffffu, mx, 16));             \
            float s = 0.f;                                                    \
            _Pragma("unroll")                                                 \
            for (int jj = 0; jj < 8; jj++) { e[jj] = fexp(e[jj] - mx); s += e[jj]; } \
            s += __shfl_xor_sync(0xffffffffu, s, 16);                         \
            const float inv = 1.f / s;                                        \
            _Pragma("unroll")                                                 \
            for (int jj = 0; jj < 8; jj++)                                    \
                sat[i * 20 + jb + jj] = e[jj] * inv;                          \
        }                                                                     \
        __syncwarp();                                                         \
        float* gbase = g_buf + (((size_t)(brow + w) * 4 + (H)) * 16) * 32 + lane; \
        _Pragma("unroll 2")                                                   \
        for (int i = 0; i < 16; i++) {                                        \
            const float4 a0 = *(const float4*)(sat + i * 20);                 \
            const float4 a1 = *(const float4*)(sat + i * 20 + 4);             \
            const float4 a2 = *(const float4*)(sat + i * 20 + 8);             \
            const float4 a3 = *(const float4*)(sat + i * 20 + 12);            \
            float gv = a0.x*HP[0] + a0.y*HP[1] + a0.z*HP[2] + a0.w*HP[3]      \
                     + a1.x*HP[4] + a1.y*HP[5] + a1.z*HP[6] + a1.w*HP[7]      \
                     + a2.x*HP[8] + a2.y*HP[9] + a2.z*HP[10]+ a2.w*HP[11]     \
                     + a3.x*HP[12]+ a3.y*HP[13]+ a3.z*HP[14]+ a3.w*HP[15];    \
            gbase[i * 32] = felu(gv);                                         \
        }                                                                     \
        __syncwarp();                                                         \
    }

__global__ __launch_bounds__(256, 2)
void gat_kernel(const float* __restrict__ hs_g,
                const float* __restrict__ Wg,
                const float* __restrict__ att,
                const float* __restrict__ s_g,
                const float* __restrict__ b1W, const float* __restrict__ b1b,
                const float* __restrict__ wfW, const float* __restrict__ wfb,
                const float* __restrict__ V1W, const float* __restrict__ V1b,
                const float* __restrict__ V2W, const float* __restrict__ V2b)
{
    extern __shared__ float sm[];
    float* shs   = sm;            // [8][16][64]
    float* sattn = sm + 8192;     // [8][16][20]

    const int tid  = threadIdx.x;
    const int lane = tid & 31;
    const int w    = tid >> 5;     // warp = local row
    const int brow = blockIdx.x * 8;

    const float4* src4 = (const float4*)(hs_g + (size_t)brow * 1024);
    for (int i = tid; i < 2048; i += 256)
        ((float4*)shs)[i] = src4[i];

    // ---- epilogue prep for row (brow+w): lane = e (EMB=32) ----
    {
        const int row = brow + w;
        float ab = 0.f, aw = 0.f, av = 0.f;
        const float* srow = s_g + (size_t)row * 128;
        #pragma unroll 4
        for (int k = 0; k < 128; k++) {
            const float sv = __ldg(srow + k);
            ab += sv * __ldg(b1W + k * 32 + lane);
            aw += sv * __ldg(wfW + k * 32 + lane);
            av += sv * __ldg(V1W + k * 32 + lane);
        }
        const float b1v = ab + __ldg(b1b + lane);
        const float wfv = fabsf(aw + __ldg(wfb + lane));
        float v1 = fmaxf(av + __ldg(V1b + lane), 0.f) * __ldg(V2W + lane);
        #pragma unroll
        for (int d = 16; d; d >>= 1)
            v1 += __shfl_xor_sync(0xffffffffu, v1, d);
        epi_buf[(size_t)row * 65 + lane]      = b1v;
        epi_buf[(size_t)row * 65 + 32 + lane] = wfv;
        if (lane == 0)
            epi_buf[(size_t)row * 65 + 64] = v1 + __ldg(V2b);
    }
    __syncthreads();

    float* sat = sattn + w * 320;             // [16][20]
    const float* hsrow = shs + w * 1024;      // [16][64]

    #pragma unroll 1
    for (int hp2 = 0; hp2 < 2; hp2++) {
        const int h0 = hp2 * 2, h1 = h0 + 1;
        float hpA[16], hpB[16];
        #pragma unroll
        for (int n = 0; n < 16; n++) { hpA[n] = 0.f; hpB[n] = 0.f; }

        const float* WcA = Wg + h0 * 32 + lane;
        const float* WcB = Wg + h1 * 32 + lane;
        #pragma unroll 4
        for (int kq = 0; kq < 16; kq++) {
            const float a0 = __ldg(WcA + (4 * kq + 0) * 128);
            const float a1 = __ldg(WcA + (4 * kq + 1) * 128);
            const float a2 = __ldg(WcA + (4 * kq + 2) * 128);
            const float a3 = __ldg(WcA + (4 * kq + 3) * 128);
            const float b0 = __ldg(WcB + (4 * kq + 0) * 128);
            const float b1 = __ldg(WcB + (4 * kq + 1) * 128);
            const float b2 = __ldg(WcB + (4 * kq + 2) * 128);
            const float b3 = __ldg(WcB + (4 * kq + 3) * 128);
            #pragma unroll
            for (int n = 0; n < 16; n++) {
                const float4 hv = *(const float4*)(hsrow + n * 64 + kq * 4);
                hpA[n] += hv.x * a0 + hv.y * a1 + hv.z * a2 + hv.w * a3;
                hpB[n] += hv.x * b0 + hv.y * b1 + hv.z * b2 + hv.w * b3;
            }
        }

        GAT_ATT(hpA, h0)
        GAT_ATT(hpB, h1)
    }
}

// =========================== Kernel B: fused mixer v7 =======================
// 16 rows/block, 256 blocks, 512 threads, 2 CTAs/SM.
// Wc column-permuted with the scatter on the cp.async DESTINATION:
//   thread loads logical float4 lq (gmem CONTIGUOUS, as R10) and stores to
//   physical slot p = (lq even) ? lq/2 : 128 + lq/2.
// => physical slot p<128 holds logical 2p; p>=128 holds logical 2(p-128)+1.
//    lane colg reads physical colg*4 / 512+colg*4 (conflict-free, as R10)
//    and owns logical cols colg*8..+7 (cheap 4-lane contraction reduce).
#define SMEM_B_FLOATS (2064 + 256 + 16384 + 8448)

__device__ __forceinline__ void cp_async16(float* s, const float* g) {
    unsigned a = (unsigned)__cvta_generic_to_shared(s);
    asm volatile("cp.async.cg.shared.global [%0], [%1], 16;" :: "r"(a), "l"(g));
}

__global__ __launch_bounds__(512, 2)
void mix_kernel(const float* __restrict__ qs_g,
                const float* __restrict__ s_g,
                const float* __restrict__ unc_g,
                const float* __restrict__ w1sW,
                const float* __restrict__ w1sb,
                float* __restrict__ out)
{
    extern __shared__ float sm[];
    float* sT    = sm;               // [129][16]  s_aug transposed
    float* sqs   = sT + 2064;        // [16][16]
    float* Wc    = sqs + 256;        // ring: 4 x [4][1024], column-permuted
    float* w1acc = Wc + 16384;       // [256][33]

    const int tid  = threadIdx.x;
    const int brow = blockIdx.x * 16;
    const int lane = tid & 31;

    for (int idx = tid; idx < 2048; idx += 512) {
        int r = idx >> 7, k = idx & 127;
        sT[k * 16 + r] = s_g[(size_t)(brow + r) * 128 + k];
    }
    if (tid < 16) sT[128 * 16 + tid] = unc_g[brow + tid];
    if (tid < 256) {
        int r = tid >> 4, n = tid & 15;
        sqs[tid] = qs_g[(size_t)(brow + r) * 16 + n];
    }
    for (int idx = tid; idx < 8448; idx += 512) w1acc[idx] = 0.f;
    __syncthreads();

    const int colg = tid & 127;      // 128 column-groups
    const int rowg = tid >> 7;       // 4 row-groups of 4
    const int cA   = colg * 4;       // PHYSICAL smem float index (conflict-free)
    const int cL   = colg * 8;       // LOGICAL gmem column (tail/bias)
    const int r0   = rowg * 4;
    const int e0   = colg >> 2;      // e = colg/4
    const int dq   = (colg & 3) * 8; // d-octet within e

    // cp.async slots: thread -> LOGICAL float4 lq (contiguous gmem),
    // scattered to PHYSICAL slot p in smem.
    const int lq0 = tid & 255,          kk0 = tid >> 8;
    const int lq1 = (tid + 512) & 255,  kk1 = (tid + 512) >> 8;
    const int p0  = (lq0 & 1) ? (128 + (lq0 >> 1)) : (lq0 >> 1);
    const int p1  = (lq1 & 1) ? (128 + (lq1 >> 1)) : (lq1 >> 1);
    const int gc0 = lq0 * 4, cc0 = p0 * 4;
    const int gc1 = lq1 * 4, cc1 = p1 * 4;

    for (int h = 0; h < 4; h++) {
        const float* Wh = w1sW + h * 1024;

        #pragma unroll
        for (int c = 0; c < 3; c++) {
            float* dst = Wc + (c & 3) * 4096;
            const float* src = Wh + (size_t)c * 4 * 4096;
            cp_async16(dst + kk0 * 1024 + cc0, src + (size_t)kk0 * 4096 + gc0);
            cp_async16(dst + kk1 * 1024 + cc1, src + (size_t)kk1 * 4096 + gc1);
            asm volatile("cp.async.commit_group;");
        }

        float acc[4][8];   // acc[i][j] = logical col cL+j, row r0+i
        #pragma unroll
        for (int i = 0; i < 4; i++)
            #pragma unroll
            for (int j = 0; j < 8; j++) acc[i][j] = 0.f;

        #pragma unroll 1
        for (int kb = 0; kb < 32; kb++) {
            if (kb < 30) asm volatile("cp.async.wait_group 2;");
            else         asm volatile("cp.async.wait_group 0;");
            __syncthreads();

            if (kb + 3 < 32) {
                float* dst = Wc + ((kb + 3) & 3) * 4096;
                const float* src = Wh + (size_t)(kb + 3) * 4 * 4096;
                cp_async16(dst + kk0 * 1024 + cc0, src + (size_t)kk0 * 4096 + gc0);
                cp_async16(dst + kk1 * 1024 + cc1, src + (size_t)kk1 * 4096 + gc1);
                asm volatile("cp.async.commit_group;");
            }

            const float* W = Wc + (kb & 3) * 4096;
            const float* sTk = sT + kb * 4 * 16;
            #pragma unroll
            for (int kk = 0; kk < 4; kk++) {
                const float4 sa = *(const float4*)(sTk + kk * 16 + r0);
                const float4 w0 = *(const float4*)(W + kk * 1024 + cA);        // logical cL..+3
                const float4 w1 = *(const float4*)(W + kk * 1024 + 512 + cA);  // logical cL+4..+7
                const float sr[4] = {sa.x, sa.y, sa.z, sa.w};
                #pragma unroll
                for (int i = 0; i < 4; i++) {
                    acc[i][0] += sr[i] * w0.x; acc[i][1] += sr[i] * w0.y;
                    acc[i][2] += sr[i] * w0.z; acc[i][3] += sr[i] * w0.w;
                    acc[i][4] += sr[i] * w1.x; acc[i][5] += sr[i] * w1.y;
                    acc[i][6] += sr[i] * w1.z; acc[i][7] += sr[i] * w1.w;
                }
            }
        }

        // tail: K row 128 (uncertainty) rank-1 + bias  (logical columns)
        {
            const float4 w0 = __ldg((const float4*)(w1sW + (size_t)128 * 4096 + h * 1024 + cL));
            const float4 w1 = __ldg((const float4*)(w1sW + (size_t)128 * 4096 + h * 1024 + cL + 4));
            const float4 b0 = __ldg((const float4*)(w1sb + h * 1024 + cL));
            const float4 b1 = __ldg((const float4*)(w1sb + h * 1024 + cL + 4));
            #pragma unroll
            for (int i = 0; i < 4; i++) {
                const float su = sT[128 * 16 + r0 + i];
                acc[i][0] += su * w0.x + b0.x; acc[i][1] += su * w0.y + b0.y;
                acc[i][2] += su * w0.z + b0.z; acc[i][3] += su * w0.w + b0.w;
                acc[i][4] += su * w1.x + b1.x; acc[i][5] += su * w1.y + b1.y;
                acc[i][6] += su * w1.z + b1.z; acc[i][7] += su * w1.w + b1.w;
            }
        }

        // contraction: w1acc[r][n][e0] += |sum_d ws[r][e0*32+d] g[r][n][d]|
        // thread covers d = dq..dq+7; 4-lane reduce (2 shfl), 1 RMW
        for (int n = 0; n < 16; n++) {
            #pragma unroll
            for (int i = 0; i < 4; i++) {
                const float* gp = g_buf +
                    (((size_t)(brow + r0 + i) * 4 + h) * 16 + n) * 32 + dq;
                const float4 g0 = __ldg((const float4*)gp);
                const float4 g1 = __ldg((const float4*)(gp + 4));
                float p = acc[i][0]*g0.x + acc[i][1]*g0.y
                        + acc[i][2]*g0.z + acc[i][3]*g0.w
                        + acc[i][4]*g1.x + acc[i][5]*g1.y
                        + acc[i][6]*g1.z + acc[i][7]*g1.w;
                p += __shfl_xor_sync(0xffffffffu, p, 1);
                p += __shfl_xor_sync(0xffffffffu, p, 2);
                if ((lane & 3) == 0)
                    w1acc[((r0 + i) * 16 + n) * 33 + e0] += fabsf(p);
            }
        }
    }
    __syncthreads();

    // ---- epilogue: warp = row (16 warps), lane = e (EMB=32) ----
    {
        const int r = tid >> 5, e = lane;
        if (r < 16) {
            float ha = 0.f;
            #pragma unroll
            for (int n = 0; n < 16; n++)
                ha += sqs[r * 16 + n] * w1acc[(r * 16 + n) * 33 + e];
            const size_t eb = (size_t)(brow + r) * 65;
            float hid = felu(0.25f * ha + epi_buf[eb + e]);
            float ys = hid * epi_buf[eb + 32 + e];
            #pragma unroll
            for (int d = 16; d; d >>= 1)
                ys += __shfl_xor_sync(0xffffffffu, ys, d);
            if (e == 0)
                out[brow + r] = ys + epi_buf[eb + 64];
        }
    }
}

// =============================================================================
extern "C" void kernel_launch(void* const* d_in, const int* in_sizes, int n_in,
                              void* d_out, int out_size)
{
    const float* qs   = (const float*)d_in[0];
    const float* st   = (const float*)d_in[1];
    const float* hs   = (const float*)d_in[2];
    const float* unc  = (const float*)d_in[3];
    const float* Wg   = (const float*)d_in[4];
    const float* att  = (const float*)d_in[5];
    const float* w1sW = (const float*)d_in[6];
    const float* w1sb = (const float*)d_in[7];
    const float* b1W  = (const float*)d_in[8];
    const float* b1b  = (const float*)d_in[9];
    const float* wfW  = (const float*)d_in[10];
    const float* wfb  = (const float*)d_in[11];
    const float* V1W  = (const float*)d_in[12];
    const float* V1b  = (const float*)d_in[13];
    const float* V2W  = (const float*)d_in[14];
    const float* V2b  = (const float*)d_in[15];
    float* out = (float*)d_out;

    (void)in_sizes; (void)n_in; (void)out_size;

    cudaFuncSetAttribute(gat_kernel, cudaFuncAttributeMaxDynamicSharedMemorySize,
                         GAT_SMEM_FLOATS * sizeof(float));
    cudaFuncSetAttribute(mix_kernel, cudaFuncAttributeMaxDynamicSharedMemorySize,
                         SMEM_B_FLOATS * sizeof(float));

    gat_kernel<<<512, 256, GAT_SMEM_FLOATS * sizeof(float)>>>(
        hs, Wg, att, st, b1W, b1b, wfW, wfb, V1W, V1b, V2W, V2b);
    mix_kernel<<<256, 512, SMEM_B_FLOATS * sizeof(float)>>>(
        qs, st, unc, w1sW, w1sb, out);
}

// round 14
// speedup vs baseline: 1.1190x; 1.1190x over previous
#include <cuda_runtime.h>
#include <cuda_bf16.h>
#include <math.h>

// ---------------------------------------------------------------------------
// DVDMixer: B = 32*128 = 4096 rows
// N_AGENTS=16, RNN_H=64, N_HEADS=4, GAT_D=32, EMB=32, SDIM=128
// fp32 CUDA-core implementation (tcgen05 not reachable through this harness
// toolchain — plain sm_103 ptxas pass; evidence R6-R9).
// cp.async note (R12/R13): per-thread src/dst permutations break LSU merging
// (~3x L2 traffic). Keep identity mapping: thread i loads float4 i -> slot i.
// ---------------------------------------------------------------------------

#define BROWS 4096

__device__ float g_buf[(size_t)BROWS * 4 * 16 * 32];   // 33.5 MB (L2-resident)
__device__ float epi_buf[(size_t)BROWS * 65];          // b1v | |wf| | v

__device__ __forceinline__ float fexp(float x) { return __expf(x); }
__device__ __forceinline__ float felu(float x) {
    return x > 0.f ? x : (__expf(x) - 1.f);
}

// ============================= Kernel A: GAT + epilogue prep ================
// (R11 two-head version — measured ~65us)
#define GAT_SMEM_FLOATS (8192 + 2560)

#define GAT_ATT(HP, H)                                                        \
    {                                                                         \
        const float asrc = __ldg(att + (H) * 64 + lane);                      \
        const float adst = __ldg(att + (H) * 64 + 32 + lane);                 \
        float srcv[16], dstv[16];                                             \
        _Pragma("unroll")                                                     \
        for (int n = 0; n < 16; n++) {                                        \
            float ps = HP[n] * asrc, pd = HP[n] * adst;                       \
            _Pragma("unroll")                                                 \
            for (int d = 16; d; d >>= 1) {                                    \
                ps += __shfl_xor_sync(0xffffffffu, ps, d);                    \
                pd += __shfl_xor_sync(0xffffffffu, pd, d);                    \
            }                                                                 \
            srcv[n] = ps; dstv[n] = pd;                                       \
        }                                                                     \
        {                                                                     \
            const int i  = lane & 15;                                         \
            const int jb = (lane >> 4) * 8;                                   \
            float e[8], mx = -1e30f;                                          \
            _Pragma("unroll")                                                 \
            for (int jj = 0; jj < 8; jj++) {                                  \
                float x = srcv[i] + dstv[jb + jj];                            \
                x = x > 0.f ? x : 0.2f * x;                                   \
                e[jj] = x;                                                    \
                mx = fmaxf(mx, x);                                            \
            }                                                                 \
            mx = fmaxf(mx, __shfl_xor_sync(0xffffffffu, mx, 16));             \
            float s = 0.f;                                                    \
            _Pragma("unroll")                                                 \
            for (int jj = 0; jj < 8; jj++) { e[jj] = fexp(e[jj] - mx); s += e[jj]; } \
            s += __shfl_xor_sync(0xffffffffu, s, 16);                         \
            const float inv = 1.f / s;                                        \
            _Pragma("unroll")                                                 \
            for (int jj = 0; jj < 8; jj++)                                    \
                sat[i * 20 + jb + jj] = e[jj] * inv;                          \
        }                                                                     \
        __syncwarp();                                                         \
        float* gbase = g_buf + (((size_t)(brow + w) * 4 + (H)) * 16) * 32 + lane; \
        _Pragma("unroll 2")                                                   \
        for (int i = 0; i < 16; i++) {                                        \
            const float4 a0 = *(const float4*)(sat + i * 20);                 \
            const float4 a1 = *(const float4*)(sat + i * 20 + 4);             \
            const float4 a2 = *(const float4*)(sat + i * 20 + 8);             \
            const float4 a3 = *(const float4*)(sat + i * 20 + 12);            \
            float gv = a0.x*HP[0] + a0.y*HP[1] + a0.z*HP[2] + a0.w*HP[3]      \
                     + a1.x*HP[4] + a1.y*HP[5] + a1.z*HP[6] + a1.w*HP[7]      \
                     + a2.x*HP[8] + a2.y*HP[9] + a2.z*HP[10]+ a2.w*HP[11]     \
                     + a3.x*HP[12]+ a3.y*HP[13]+ a3.z*HP[14]+ a3.w*HP[15];    \
            gbase[i * 32] = felu(gv);                                         \
        }                                                                     \
        __syncwarp();                                                         \
    }

__global__ __launch_bounds__(256, 2)
void gat_kernel(const float* __restrict__ hs_g,
                const float* __restrict__ Wg,
                const float* __restrict__ att,
                const float* __restrict__ s_g,
                const float* __restrict__ b1W, const float* __restrict__ b1b,
                const float* __restrict__ wfW, const float* __restrict__ wfb,
                const float* __restrict__ V1W, const float* __restrict__ V1b,
                const float* __restrict__ V2W, const float* __restrict__ V2b)
{
    extern __shared__ float sm[];
    float* shs   = sm;            // [8][16][64]
    float* sattn = sm + 8192;     // [8][16][20]

    const int tid  = threadIdx.x;
    const int lane = tid & 31;
    const int w    = tid >> 5;     // warp = local row
    const int brow = blockIdx.x * 8;

    const float4* src4 = (const float4*)(hs_g + (size_t)brow * 1024);
    for (int i = tid; i < 2048; i += 256)
        ((float4*)shs)[i] = src4[i];

    // ---- epilogue prep for row (brow+w): lane = e (EMB=32) ----
    {
        const int row = brow + w;
        float ab = 0.f, aw = 0.f, av = 0.f;
        const float* srow = s_g + (size_t)row * 128;
        #pragma unroll 4
        for (int k = 0; k < 128; k++) {
            const float sv = __ldg(srow + k);
            ab += sv * __ldg(b1W + k * 32 + lane);
            aw += sv * __ldg(wfW + k * 32 + lane);
            av += sv * __ldg(V1W + k * 32 + lane);
        }
        const float b1v = ab + __ldg(b1b + lane);
        const float wfv = fabsf(aw + __ldg(wfb + lane));
        float v1 = fmaxf(av + __ldg(V1b + lane), 0.f) * __ldg(V2W + lane);
        #pragma unroll
        for (int d = 16; d; d >>= 1)
            v1 += __shfl_xor_sync(0xffffffffu, v1, d);
        epi_buf[(size_t)row * 65 + lane]      = b1v;
        epi_buf[(size_t)row * 65 + 32 + lane] = wfv;
        if (lane == 0)
            epi_buf[(size_t)row * 65 + 64] = v1 + __ldg(V2b);
    }
    __syncthreads();

    float* sat = sattn + w * 320;             // [16][20]
    const float* hsrow = shs + w * 1024;      // [16][64]

    #pragma unroll 1
    for (int hp2 = 0; hp2 < 2; hp2++) {
        const int h0 = hp2 * 2, h1 = h0 + 1;
        float hpA[16], hpB[16];
        #pragma unroll
        for (int n = 0; n < 16; n++) { hpA[n] = 0.f; hpB[n] = 0.f; }

        const float* WcA = Wg + h0 * 32 + lane;
        const float* WcB = Wg + h1 * 32 + lane;
        #pragma unroll 4
        for (int kq = 0; kq < 16; kq++) {
            const float a0 = __ldg(WcA + (4 * kq + 0) * 128);
            const float a1 = __ldg(WcA + (4 * kq + 1) * 128);
            const float a2 = __ldg(WcA + (4 * kq + 2) * 128);
            const float a3 = __ldg(WcA + (4 * kq + 3) * 128);
            const float b0 = __ldg(WcB + (4 * kq + 0) * 128);
            const float b1 = __ldg(WcB + (4 * kq + 1) * 128);
            const float b2 = __ldg(WcB + (4 * kq + 2) * 128);
            const float b3 = __ldg(WcB + (4 * kq + 3) * 128);
            #pragma unroll
            for (int n = 0; n < 16; n++) {
                const float4 hv = *(const float4*)(hsrow + n * 64 + kq * 4);
                hpA[n] += hv.x * a0 + hv.y * a1 + hv.z * a2 + hv.w * a3;
                hpB[n] += hv.x * b0 + hv.y * b1 + hv.z * b2 + hv.w * b3;
            }
        }

        GAT_ATT(hpA, h0)
        GAT_ATT(hpB, h1)
    }
}

// =========================== Kernel B: fused mixer (R10 + split-reduce) =====
// 16 rows/block, 256 blocks, 512 threads, 2 CTAs/SM.
// Identity cp.async mapping; conflict-free LDS (cA = colg*4, groups at +512).
// Contraction: thread owns e0 (=colg>>3) and e0+16 at d0=(colg&7)*4;
// split-reduce: stage-1 xor4 routes p0->low half / p1->high half of the
// 8-lane octet, then xor1+xor2 => 4 shfl + 1 RMW per (n,i).
#define SMEM_B_FLOATS (2064 + 256 + 16384 + 8448)

__device__ __forceinline__ void cp_async16(float* s, const float* g) {
    unsigned a = (unsigned)__cvta_generic_to_shared(s);
    asm volatile("cp.async.cg.shared.global [%0], [%1], 16;" :: "r"(a), "l"(g));
}

__global__ __launch_bounds__(512, 2)
void mix_kernel(const float* __restrict__ qs_g,
                const float* __restrict__ s_g,
                const float* __restrict__ unc_g,
                const float* __restrict__ w1sW,
                const float* __restrict__ w1sb,
                float* __restrict__ out)
{
    extern __shared__ float sm[];
    float* sT    = sm;               // [129][16]  s_aug transposed
    float* sqs   = sT + 2064;        // [16][16]
    float* Wc    = sqs + 256;        // ring: 4 x [4][1024]
    float* w1acc = Wc + 16384;       // [256][33]

    const int tid  = threadIdx.x;
    const int brow = blockIdx.x * 16;
    const int lane = tid & 31;

    for (int idx = tid; idx < 2048; idx += 512) {
        int r = idx >> 7, k = idx & 127;
        sT[k * 16 + r] = s_g[(size_t)(brow + r) * 128 + k];
    }
    if (tid < 16) sT[128 * 16 + tid] = unc_g[brow + tid];
    if (tid < 256) {
        int r = tid >> 4, n = tid & 15;
        sqs[tid] = qs_g[(size_t)(brow + r) * 16 + n];
    }
    for (int idx = tid; idx < 8448; idx += 512) w1acc[idx] = 0.f;
    __syncthreads();

    const int colg = tid & 127;      // 128 column-groups
    const int rowg = tid >> 7;       // 4 row-groups of 4
    const int cA   = colg * 4;       // cols cA..+3 and 512+cA..+3
    const int r0   = rowg * 4;
    const int e0   = colg >> 3;
    const int d0   = (colg & 7) * 4;

    const int kk0 = tid >> 8,           cc0 = (tid & 255) * 4;
    const int kk1 = (tid + 512) >> 8,   cc1 = ((tid + 512) & 255) * 4;

    for (int h = 0; h < 4; h++) {
        const float* Wh = w1sW + h * 1024;

        #pragma unroll
        for (int c = 0; c < 3; c++) {
            float* dst = Wc + (c & 3) * 4096;
            const float* src = Wh + (size_t)c * 4 * 4096;
            cp_async16(dst + kk0 * 1024 + cc0, src + (size_t)kk0 * 4096 + cc0);
            cp_async16(dst + kk1 * 1024 + cc1, src + (size_t)kk1 * 4096 + cc1);
            asm volatile("cp.async.commit_group;");
        }

        float acc[4][8];
        #pragma unroll
        for (int i = 0; i < 4; i++)
            #pragma unroll
            for (int j = 0; j < 8; j++) acc[i][j] = 0.f;

        #pragma unroll 1
        for (int kb = 0; kb < 32; kb++) {
            if (kb < 30) asm volatile("cp.async.wait_group 2;");
            else         asm volatile("cp.async.wait_group 0;");
            __syncthreads();

            if (kb + 3 < 32) {
                float* dst = Wc + ((kb + 3) & 3) * 4096;
                const float* src = Wh + (size_t)(kb + 3) * 4 * 4096;
                cp_async16(dst + kk0 * 1024 + cc0, src + (size_t)kk0 * 4096 + cc0);
                cp_async16(dst + kk1 * 1024 + cc1, src + (size_t)kk1 * 4096 + cc1);
                asm volatile("cp.async.commit_group;");
            }

            const float* W = Wc + (kb & 3) * 4096;
            const float* sTk = sT + kb * 4 * 16;
            #pragma unroll
            for (int kk = 0; kk < 4; kk++) {
                const float4 sa = *(const float4*)(sTk + kk * 16 + r0);
                const float4 w0 = *(const float4*)(W + kk * 1024 + cA);
                const float4 w1 = *(const float4*)(W + kk * 1024 + 512 + cA);
                const float sr[4] = {sa.x, sa.y, sa.z, sa.w};
                #pragma unroll
                for (int i = 0; i < 4; i++) {
                    acc[i][0] += sr[i] * w0.x; acc[i][1] += sr[i] * w0.y;
                    acc[i][2] += sr[i] * w0.z; acc[i][3] += sr[i] * w0.w;
                    acc[i][4] += sr[i] * w1.x; acc[i][5] += sr[i] * w1.y;
                    acc[i][6] += sr[i] * w1.z; acc[i][7] += sr[i] * w1.w;
                }
            }
        }

        // tail: K row 128 (uncertainty) rank-1 + bias
        {
            const float4 w0 = __ldg((const float4*)(w1sW + (size_t)128 * 4096 + h * 1024 + cA));
            const float4 w1 = __ldg((const float4*)(w1sW + (size_t)128 * 4096 + h * 1024 + 512 + cA));
            const float4 b0 = __ldg((const float4*)(w1sb + h * 1024 + cA));
            const float4 b1 = __ldg((const float4*)(w1sb + h * 1024 + 512 + cA));
            #pragma unroll
            for (int i = 0; i < 4; i++) {
                const float su = sT[128 * 16 + r0 + i];
                acc[i][0] += su * w0.x + b0.x; acc[i][1] += su * w0.y + b0.y;
                acc[i][2] += su * w0.z + b0.z; acc[i][3] += su * w0.w + b0.w;
                acc[i][4] += su * w1.x + b1.x; acc[i][5] += su * w1.y + b1.y;
                acc[i][6] += su * w1.z + b1.z; acc[i][7] += su * w1.w + b1.w;
            }
        }

        // contraction: w1acc[r][n][e] += |sum_d ws[r][e*32+d] g[r][n][d]|
        // split-reduce over the 8-lane d-octet: 4 shfl + 1 RMW
        for (int n = 0; n < 16; n++) {
            #pragma unroll
            for (int i = 0; i < 4; i++) {
                const float4 gv = __ldg((const float4*)(
                    g_buf + (((size_t)(brow + r0 + i) * 4 + h) * 16 + n) * 32 + d0));
                float p0 = acc[i][0]*gv.x + acc[i][1]*gv.y + acc[i][2]*gv.z + acc[i][3]*gv.w;
                float p1 = acc[i][4]*gv.x + acc[i][5]*gv.y + acc[i][6]*gv.z + acc[i][7]*gv.w;
                const float t0 = __shfl_xor_sync(0xffffffffu, p0, 4);
                const float t1 = __shfl_xor_sync(0xffffffffu, p1, 4);
                float q = (lane & 4) ? (p1 + t1) : (p0 + t0);
                q += __shfl_xor_sync(0xffffffffu, q, 1);
                q += __shfl_xor_sync(0xffffffffu, q, 2);
                const int l7 = lane & 7;
                if (l7 == 0)
                    w1acc[((r0 + i) * 16 + n) * 33 + e0] += fabsf(q);
                else if (l7 == 4)
                    w1acc[((r0 + i) * 16 + n) * 33 + e0 + 16] += fabsf(q);
            }
        }
    }
    __syncthreads();

    // ---- epilogue: warp = row (16 warps), lane = e (EMB=32) ----
    {
        const int r = tid >> 5, e = lane;
        if (r < 16) {
            float ha = 0.f;
            #pragma unroll
            for (int n = 0; n < 16; n++)
                ha += sqs[r * 16 + n] * w1acc[(r * 16 + n) * 33 + e];
            const size_t eb = (size_t)(brow + r) * 65;
            float hid = felu(0.25f * ha + epi_buf[eb + e]);
            float ys = hid * epi_buf[eb + 32 + e];
            #pragma unroll
            for (int d = 16; d; d >>= 1)
                ys += __shfl_xor_sync(0xffffffffu, ys, d);
            if (e == 0)
                out[brow + r] = ys + epi_buf[eb + 64];
        }
    }
}

// =============================================================================
extern "C" void kernel_launch(void* const* d_in, const int* in_sizes, int n_in,
                              void* d_out, int out_size)
{
    const float* qs   = (const float*)d_in[0];
    const float* st   = (const float*)d_in[1];
    const float* hs   = (const float*)d_in[2];
    const float* unc  = (const float*)d_in[3];
    const float* Wg   = (const float*)d_in[4];
    const float* att  = (const float*)d_in[5];
    const float* w1sW = (const float*)d_in[6];
    const float* w1sb = (const float*)d_in[7];
    const float* b1W  = (const float*)d_in[8];
    const float* b1b  = (const float*)d_in[9];
    const float* wfW  = (const float*)d_in[10];
    const float* wfb  = (const float*)d_in[11];
    const float* V1W  = (const float*)d_in[12];
    const float* V1b  = (const float*)d_in[13];
    const float* V2W  = (const float*)d_in[14];
    const float* V2b  = (const float*)d_in[15];
    float* out = (float*)d_out;

    (void)in_sizes; (void)n_in; (void)out_size;

    cudaFuncSetAttribute(gat_kernel, cudaFuncAttributeMaxDynamicSharedMemorySize,
                         GAT_SMEM_FLOATS * sizeof(float));
    cudaFuncSetAttribute(mix_kernel, cudaFuncAttributeMaxDynamicSharedMemorySize,
                         SMEM_B_FLOATS * sizeof(float));

    gat_kernel<<<512, 256, GAT_SMEM_FLOATS * sizeof(float)>>>(
        hs, Wg, att, st, b1W, b1b, wfW, wfb, V1W, V1b, V2W, V2b);
    mix_kernel<<<256, 512, SMEM_B_FLOATS * sizeof(float)>>>(
        qs, st, unc, w1sW, w1sb, out);
}

// round 15
// speedup vs baseline: 1.2887x; 1.1516x over previous
#include <cuda_runtime.h>
#include <cuda_bf16.h>
#include <math.h>

// ---------------------------------------------------------------------------
// DVDMixer: B = 32*128 = 4096 rows
// N_AGENTS=16, RNN_H=64, N_HEADS=4, GAT_D=32, EMB=32, SDIM=128
// fp32 CUDA-core implementation (tcgen05 not reachable through this harness
// toolchain — plain sm_103 ptxas pass; evidence R6-R9).
// mix_kernel: EXACT R10 version (measured 209.1us). Do not modify — R4
// (FFMA2), R11 (remap), R12/R13 (permutation), R14 (split-reduce) all
// regressed it. gat_kernel: R11 two-head version (measured ~64.9us).
// ---------------------------------------------------------------------------

#define BROWS 4096

__device__ float g_buf[(size_t)BROWS * 4 * 16 * 32];   // 33.5 MB (L2-resident)
__device__ float epi_buf[(size_t)BROWS * 65];          // b1v | |wf| | v

__device__ __forceinline__ float fexp(float x) { return __expf(x); }
__device__ __forceinline__ float felu(float x) {
    return x > 0.f ? x : (__expf(x) - 1.f);
}

// ============================= Kernel A: GAT + epilogue prep ================
// (R11 two-head version — measured ~64.9us)
#define GAT_SMEM_FLOATS (8192 + 2560)

#define GAT_ATT(HP, H)                                                        \
    {                                                                         \
        const float asrc = __ldg(att + (H) * 64 + lane);                      \
        const float adst = __ldg(att + (H) * 64 + 32 + lane);                 \
        float srcv[16], dstv[16];                                             \
        _Pragma("unroll")                                                     \
        for (int n = 0; n < 16; n++) {                                        \
            float ps = HP[n] * asrc, pd = HP[n] * adst;                       \
            _Pragma("unroll")                                                 \
            for (int d = 16; d; d >>= 1) {                                    \
                ps += __shfl_xor_sync(0xffffffffu, ps, d);                    \
                pd += __shfl_xor_sync(0xffffffffu, pd, d);                    \
            }                                                                 \
            srcv[n] = ps; dstv[n] = pd;                                       \
        }                                                                     \
        {                                                                     \
            const int i  = lane & 15;                                         \
            const int jb = (lane >> 4) * 8;                                   \
            float e[8], mx = -1e30f;                                          \
            _Pragma("unroll")                                                 \
            for (int jj = 0; jj < 8; jj++) {                                  \
                float x = srcv[i] + dstv[jb + jj];                            \
                x = x > 0.f ? x : 0.2f * x;                                   \
                e[jj] = x;                                                    \
                mx = fmaxf(mx, x);                                            \
            }                                                                 \
            mx = fmaxf(mx, __shfl_xor_sync(0xffffffffu, mx, 16));             \
            float s = 0.f;                                                    \
            _Pragma("unroll")                                                 \
            for (int jj = 0; jj < 8; jj++) { e[jj] = fexp(e[jj] - mx); s += e[jj]; } \
            s += __shfl_xor_sync(0xffffffffu, s, 16);                         \
            const float inv = 1.f / s;                                        \
            _Pragma("unroll")                                                 \
            for (int jj = 0; jj < 8; jj++)                                    \
                sat[i * 20 + jb + jj] = e[jj] * inv;                          \
        }                                                                     \
        __syncwarp();                                                         \
        float* gbase = g_buf + (((size_t)(brow + w) * 4 + (H)) * 16) * 32 + lane; \
        _Pragma("unroll 2")                                                   \
        for (int i = 0; i < 16; i++) {                                        \
            const float4 a0 = *(const float4*)(sat + i * 20);                 \
            const float4 a1 = *(const float4*)(sat + i * 20 + 4);             \
            const float4 a2 = *(const float4*)(sat + i * 20 + 8);             \
            const float4 a3 = *(const float4*)(sat + i * 20 + 12);            \
            float gv = a0.x*HP[0] + a0.y*HP[1] + a0.z*HP[2] + a0.w*HP[3]      \
                     + a1.x*HP[4] + a1.y*HP[5] + a1.z*HP[6] + a1.w*HP[7]      \
                     + a2.x*HP[8] + a2.y*HP[9] + a2.z*HP[10]+ a2.w*HP[11]     \
                     + a3.x*HP[12]+ a3.y*HP[13]+ a3.z*HP[14]+ a3.w*HP[15];    \
            gbase[i * 32] = felu(gv);                                         \
        }                                                                     \
        __syncwarp();                                                         \
    }

__global__ __launch_bounds__(256, 2)
void gat_kernel(const float* __restrict__ hs_g,
                const float* __restrict__ Wg,
                const float* __restrict__ att,
                const float* __restrict__ s_g,
                const float* __restrict__ b1W, const float* __restrict__ b1b,
                const float* __restrict__ wfW, const float* __restrict__ wfb,
                const float* __restrict__ V1W, const float* __restrict__ V1b,
                const float* __restrict__ V2W, const float* __restrict__ V2b)
{
    extern __shared__ float sm[];
    float* shs   = sm;            // [8][16][64]
    float* sattn = sm + 8192;     // [8][16][20]

    const int tid  = threadIdx.x;
    const int lane = tid & 31;
    const int w    = tid >> 5;     // warp = local row
    const int brow = blockIdx.x * 8;

    const float4* src4 = (const float4*)(hs_g + (size_t)brow * 1024);
    for (int i = tid; i < 2048; i += 256)
        ((float4*)shs)[i] = src4[i];

    // ---- epilogue prep for row (brow+w): lane = e (EMB=32) ----
    {
        const int row = brow + w;
        float ab = 0.f, aw = 0.f, av = 0.f;
        const float* srow = s_g + (size_t)row * 128;
        #pragma unroll 4
        for (int k = 0; k < 128; k++) {
            const float sv = __ldg(srow + k);
            ab += sv * __ldg(b1W + k * 32 + lane);
            aw += sv * __ldg(wfW + k * 32 + lane);
            av += sv * __ldg(V1W + k * 32 + lane);
        }
        const float b1v = ab + __ldg(b1b + lane);
        const float wfv = fabsf(aw + __ldg(wfb + lane));
        float v1 = fmaxf(av + __ldg(V1b + lane), 0.f) * __ldg(V2W + lane);
        #pragma unroll
        for (int d = 16; d; d >>= 1)
            v1 += __shfl_xor_sync(0xffffffffu, v1, d);
        epi_buf[(size_t)row * 65 + lane]      = b1v;
        epi_buf[(size_t)row * 65 + 32 + lane] = wfv;
        if (lane == 0)
            epi_buf[(size_t)row * 65 + 64] = v1 + __ldg(V2b);
    }
    __syncthreads();

    float* sat = sattn + w * 320;             // [16][20]
    const float* hsrow = shs + w * 1024;      // [16][64]

    #pragma unroll 1
    for (int hp2 = 0; hp2 < 2; hp2++) {
        const int h0 = hp2 * 2, h1 = h0 + 1;
        float hpA[16], hpB[16];
        #pragma unroll
        for (int n = 0; n < 16; n++) { hpA[n] = 0.f; hpB[n] = 0.f; }

        const float* WcA = Wg + h0 * 32 + lane;
        const float* WcB = Wg + h1 * 32 + lane;
        #pragma unroll 4
        for (int kq = 0; kq < 16; kq++) {
            const float a0 = __ldg(WcA + (4 * kq + 0) * 128);
            const float a1 = __ldg(WcA + (4 * kq + 1) * 128);
            const float a2 = __ldg(WcA + (4 * kq + 2) * 128);
            const float a3 = __ldg(WcA + (4 * kq + 3) * 128);
            const float b0 = __ldg(WcB + (4 * kq + 0) * 128);
            const float b1 = __ldg(WcB + (4 * kq + 1) * 128);
            const float b2 = __ldg(WcB + (4 * kq + 2) * 128);
            const float b3 = __ldg(WcB + (4 * kq + 3) * 128);
            #pragma unroll
            for (int n = 0; n < 16; n++) {
                const float4 hv = *(const float4*)(hsrow + n * 64 + kq * 4);
                hpA[n] += hv.x * a0 + hv.y * a1 + hv.z * a2 + hv.w * a3;
                hpB[n] += hv.x * b0 + hv.y * b1 + hv.z * b2 + hv.w * b3;
            }
        }

        GAT_ATT(hpA, h0)
        GAT_ATT(hpB, h1)
    }
}

// =========================== Kernel B: fused mixer (EXACT R10) ==============
// 16 rows/block, 256 blocks, 512 threads, 2 CTAs/SM.  Measured 209.1us.
#define SMEM_B_FLOATS (2064 + 256 + 16384 + 8448)

__device__ __forceinline__ void cp_async16(float* s, const float* g) {
    unsigned a = (unsigned)__cvta_generic_to_shared(s);
    asm volatile("cp.async.cg.shared.global [%0], [%1], 16;" :: "r"(a), "l"(g));
}

__global__ __launch_bounds__(512, 2)
void mix_kernel(const float* __restrict__ qs_g,
                const float* __restrict__ s_g,
                const float* __restrict__ unc_g,
                const float* __restrict__ w1sW,
                const float* __restrict__ w1sb,
                float* __restrict__ out)
{
    extern __shared__ float sm[];
    float* sT    = sm;               // [129][16]  s_aug transposed
    float* sqs   = sT + 2064;        // [16][16]
    float* Wc    = sqs + 256;        // ring: 4 x [4][1024]
    float* w1acc = Wc + 16384;       // [256][33]

    const int tid  = threadIdx.x;
    const int brow = blockIdx.x * 16;
    const int lane = tid & 31;

    for (int idx = tid; idx < 2048; idx += 512) {
        int r = idx >> 7, k = idx & 127;
        sT[k * 16 + r] = s_g[(size_t)(brow + r) * 128 + k];
    }
    if (tid < 16) sT[128 * 16 + tid] = unc_g[brow + tid];
    if (tid < 256) {
        int r = tid >> 4, n = tid & 15;
        sqs[tid] = qs_g[(size_t)(brow + r) * 16 + n];
    }
    for (int idx = tid; idx < 8448; idx += 512) w1acc[idx] = 0.f;
    __syncthreads();

    const int colg = tid & 127;      // 128 column-groups
    const int rowg = tid >> 7;       // 4 row-groups of 4
    const int cA   = colg * 4;       // cols cA..+3 and 512+cA..+3
    const int r0   = rowg * 4;
    const int e0   = colg >> 3;
    const int d0   = (colg & 7) * 4;

    const int kk0 = tid >> 8,           cc0 = (tid & 255) * 4;
    const int kk1 = (tid + 512) >> 8,   cc1 = ((tid + 512) & 255) * 4;

    for (int h = 0; h < 4; h++) {
        const float* Wh = w1sW + h * 1024;

        #pragma unroll
        for (int c = 0; c < 3; c++) {
            float* dst = Wc + (c & 3) * 4096;
            const float* src = Wh + (size_t)c * 4 * 4096;
            cp_async16(dst + kk0 * 1024 + cc0, src + (size_t)kk0 * 4096 + cc0);
            cp_async16(dst + kk1 * 1024 + cc1, src + (size_t)kk1 * 4096 + cc1);
            asm volatile("cp.async.commit_group;");
        }

        float acc[4][8];
        #pragma unroll
        for (int i = 0; i < 4; i++)
            #pragma unroll
            for (int j = 0; j < 8; j++) acc[i][j] = 0.f;

        #pragma unroll 1
        for (int kb = 0; kb < 32; kb++) {
            if (kb < 30) asm volatile("cp.async.wait_group 2;");
            else         asm volatile("cp.async.wait_group 0;");
            __syncthreads();

            if (kb + 3 < 32) {
                float* dst = Wc + ((kb + 3) & 3) * 4096;
                const float* src = Wh + (size_t)(kb + 3) * 4 * 4096;
                cp_async16(dst + kk0 * 1024 + cc0, src + (size_t)kk0 * 4096 + cc0);
                cp_async16(dst + kk1 * 1024 + cc1, src + (size_t)kk1 * 4096 + cc1);
                asm volatile("cp.async.commit_group;");
            }

            const float* W = Wc + (kb & 3) * 4096;
            const float* sTk = sT + kb * 4 * 16;
            #pragma unroll
            for (int kk = 0; kk < 4; kk++) {
                const float4 sa = *(const float4*)(sTk + kk * 16 + r0);
                const float4 w0 = *(const float4*)(W + kk * 1024 + cA);
                const float4 w1 = *(const float4*)(W + kk * 1024 + 512 + cA);
                const float sr[4] = {sa.x, sa.y, sa.z, sa.w};
                #pragma unroll
                for (int i = 0; i < 4; i++) {
                    acc[i][0] += sr[i] * w0.x; acc[i][1] += sr[i] * w0.y;
                    acc[i][2] += sr[i] * w0.z; acc[i][3] += sr[i] * w0.w;
                    acc[i][4] += sr[i] * w1.x; acc[i][5] += sr[i] * w1.y;
                    acc[i][6] += sr[i] * w1.z; acc[i][7] += sr[i] * w1.w;
                }
            }
        }

        // tail: K row 128 (uncertainty) rank-1 + bias
        {
            const float4 w0 = __ldg((const float4*)(w1sW + (size_t)128 * 4096 + h * 1024 + cA));
            const float4 w1 = __ldg((const float4*)(w1sW + (size_t)128 * 4096 + h * 1024 + 512 + cA));
            const float4 b0 = __ldg((const float4*)(w1sb + h * 1024 + cA));
            const float4 b1 = __ldg((const float4*)(w1sb + h * 1024 + 512 + cA));
            #pragma unroll
            for (int i = 0; i < 4; i++) {
                const float su = sT[128 * 16 + r0 + i];
                acc[i][0] += su * w0.x + b0.x; acc[i][1] += su * w0.y + b0.y;
                acc[i][2] += su * w0.z + b0.z; acc[i][3] += su * w0.w + b0.w;
                acc[i][4] += su * w1.x + b1.x; acc[i][5] += su * w1.y + b1.y;
                acc[i][6] += su * w1.z + b1.z; acc[i][7] += su * w1.w + b1.w;
            }
        }

        // contraction: w1acc[r][n][e] += |sum_d ws[r][e*32+d] g[r][n][d]|
        for (int n = 0; n < 16; n++) {
            #pragma unroll
            for (int i = 0; i < 4; i++) {
                const float4 gv = __ldg((const float4*)(
                    g_buf + (((size_t)(brow + r0 + i) * 4 + h) * 16 + n) * 32 + d0));
                float p0 = acc[i][0]*gv.x + acc[i][1]*gv.y + acc[i][2]*gv.z + acc[i][3]*gv.w;
                float p1 = acc[i][4]*gv.x + acc[i][5]*gv.y + acc[i][6]*gv.z + acc[i][7]*gv.w;
                p0 += __shfl_xor_sync(0xffffffffu, p0, 1);
                p1 += __shfl_xor_sync(0xffffffffu, p1, 1);
                p0 += __shfl_xor_sync(0xffffffffu, p0, 2);
                p1 += __shfl_xor_sync(0xffffffffu, p1, 2);
                p0 += __shfl_xor_sync(0xffffffffu, p0, 4);
                p1 += __shfl_xor_sync(0xffffffffu, p1, 4);
                if ((lane & 7) == 0) {
                    float* wa = w1acc + ((r0 + i) * 16 + n) * 33;
                    wa[e0]      += fabsf(p0);
                    wa[e0 + 16] += fabsf(p1);
                }
            }
        }
    }
    __syncthreads();

    // ---- epilogue: warp = row (16 warps), lane = e (EMB=32) ----
    {
        const int r = tid >> 5, e = lane;
        if (r < 16) {
            float ha = 0.f;
            #pragma unroll
            for (int n = 0; n < 16; n++)
                ha += sqs[r * 16 + n] * w1acc[(r * 16 + n) * 33 + e];
            const size_t eb = (size_t)(brow + r) * 65;
            float hid = felu(0.25f * ha + epi_buf[eb + e]);
            float ys = hid * epi_buf[eb + 32 + e];
            #pragma unroll
            for (int d = 16; d; d >>= 1)
                ys += __shfl_xor_sync(0xffffffffu, ys, d);
            if (e == 0)
                out[brow + r] = ys + epi_buf[eb + 64];
        }
    }
}

// =============================================================================
extern "C" void kernel_launch(void* const* d_in, const int* in_sizes, int n_in,
                              void* d_out, int out_size)
{
    const float* qs   = (const float*)d_in[0];
    const float* st   = (const float*)d_in[1];
    const float* hs   = (const float*)d_in[2];
    const float* unc  = (const float*)d_in[3];
    const float* Wg   = (const float*)d_in[4];
    const float* att  = (const float*)d_in[5];
    const float* w1sW = (const float*)d_in[6];
    const float* w1sb = (const float*)d_in[7];
    const float* b1W  = (const float*)d_in[8];
    const float* b1b  = (const float*)d_in[9];
    const float* wfW  = (const float*)d_in[10];
    const float* wfb  = (const float*)d_in[11];
    const float* V1W  = (const float*)d_in[12];
    const float* V1b  = (const float*)d_in[13];
    const float* V2W  = (const float*)d_in[14];
    const float* V2b  = (const float*)d_in[15];
    float* out = (float*)d_out;

    (void)in_sizes; (void)n_in; (void)out_size;

    cudaFuncSetAttribute(gat_kernel, cudaFuncAttributeMaxDynamicSharedMemorySize,
                         GAT_SMEM_FLOATS * sizeof(float));
    cudaFuncSetAttribute(mix_kernel, cudaFuncAttributeMaxDynamicSharedMemorySize,
                         SMEM_B_FLOATS * sizeof(float));

    gat_kernel<<<512, 256, GAT_SMEM_FLOATS * sizeof(float)>>>(
        hs, Wg, att, st, b1W, b1b, wfW, wfb, V1W, V1b, V2W, V2b);
    mix_kernel<<<256, 512, SMEM_B_FLOATS * sizeof(float)>>>(
        qs, st, unc, w1sW, w1sb, out);
}